// round 17
// baseline (speedup 1.0000x reference)
#include <cuda_runtime.h>
#include <cuda_bf16.h>
#include <math.h>
#include <stdint.h>

// Problem constants (B=1)
#define H_   8
#define S_   1024
#define D_   64
#define KG_  10

// Tiling
#define BI   128
#define BJ   32
#define NT   256
#define NSPLIT 4
#define TILES_PER_SPLIT (S_ / BJ / NSPLIT)   // 8

// LUT
#define LUTN    2048
#define RANGE_D 10.0f
#define RANGE_E 5.0f

// strides (bf16 elements): 72 for d=64 tiles (144 B), 40 for P (80 B).
// 144 B = 36 words mod 32 = 4 -> ldmatrix phases conflict-free; 16B aligned.
// 80 B = 20 words; 20*l mod 32 distinct over l=0..7 -> conflict-free.
#define QS 72
#define PS 40

// smem element offsets (bf16)
#define OFF_QHI 0
#define OFF_QLO 9216
#define OFF_KHI 18432     // 2 buffers x 2304
#define OFF_KLO 23040
#define OFF_VHI 27648
#define OFF_VLO 32256
#define OFF_PHI 36864
#define OFF_PLO 41984
#define SMEM_ELEMS 47104  // 94208 bytes
#define KVBUF_BYTES 4608  // 2304 el per buffer

__device__ float2 g_lutD[LUTN];
__device__ float2 g_lutE[LUTN];
__device__ float  g_vals[2][LUTN + 1];
// pre-split bf16 operands: per row, 64 hi || 64 lo  (256 bytes/row)
__device__ __nv_bfloat16 g_Qsp[H_ * S_ * 128];
__device__ __nv_bfloat16 g_Ksp[H_ * S_ * 128];
__device__ __nv_bfloat16 g_Vsp[H_ * S_ * 128];
// split-KV scratch (static __device__: no allocation)
__device__ float  g_Opart[NSPLIT][H_ * S_ * D_];
__device__ float2 g_ML[NSPLIT][H_ * S_];

// ---------------------------------------------------------------------------
// helpers
// ---------------------------------------------------------------------------
__device__ __forceinline__ void split_bf(float x, float& hi, float& lo) {
    __nv_bfloat16 h = __float2bfloat16_rn(x);
    hi = __bfloat162float(h);
    lo = x - hi;
}
__device__ __forceinline__ uint32_t pack_bf2(float a, float b) {
    __nv_bfloat162 t = __floats2bfloat162_rn(a, b);
    return *reinterpret_cast<uint32_t*>(&t);
}
__device__ __forceinline__ void mma_bf16(float* c, const uint32_t* a, const uint32_t* b) {
    asm volatile(
        "mma.sync.aligned.m16n8k16.row.col.f32.bf16.bf16.f32 "
        "{%0,%1,%2,%3}, {%4,%5,%6,%7}, {%8,%9}, {%0,%1,%2,%3};"
        : "+f"(c[0]), "+f"(c[1]), "+f"(c[2]), "+f"(c[3])
        : "r"(a[0]), "r"(a[1]), "r"(a[2]), "r"(a[3]), "r"(b[0]), "r"(b[1]));
}
__device__ __forceinline__ void ldsm_x4(uint32_t addr, uint32_t* r) {
    asm volatile("ldmatrix.sync.aligned.m8n8.x4.shared.b16 {%0,%1,%2,%3}, [%4];"
        : "=r"(r[0]), "=r"(r[1]), "=r"(r[2]), "=r"(r[3]) : "r"(addr));
}
__device__ __forceinline__ void ldsm_x4_trans(uint32_t addr, uint32_t* r) {
    asm volatile("ldmatrix.sync.aligned.m8n8.x4.trans.shared.b16 {%0,%1,%2,%3}, [%4];"
        : "=r"(r[0]), "=r"(r[1]), "=r"(r[2]), "=r"(r[3]) : "r"(addr));
}
__device__ __forceinline__ void cp_async16(uint32_t dst, const void* src) {
    asm volatile("cp.async.cg.shared.global [%0], [%1], 16;"
        :: "r"(dst), "l"(src) : "memory");
}
__device__ __forceinline__ void cp_commit() {
    asm volatile("cp.async.commit_group;" ::: "memory");
}
__device__ __forceinline__ void cp_wait0() {
    asm volatile("cp.async.wait_group 0;" ::: "memory");
}

// ---------------------------------------------------------------------------
// LUT construction
// ---------------------------------------------------------------------------
__device__ __forceinline__ float gelu_exact(float x) {
    return 0.5f * x * (1.0f + erff(x * 0.70710678118654752f));
}

__device__ float bias_eval(float x,
                           const float* __restrict__ mu, const float* __restrict__ sg,
                           const float* __restrict__ bb,
                           const float* __restrict__ W1, const float* __restrict__ b1,
                           const float* __restrict__ W2, float b2v) {
    float psi[KG_];
#pragma unroll
    for (int k = 0; k < KG_; k++) {
        float s = sg[k];
        float z = (x + bb[k] - mu[k]) / s;
        psi[k] = expf(-0.5f * z * z) * (0.3989422804014327f / s);
    }
    float acc = b2v;
#pragma unroll
    for (int l = 0; l < KG_; l++) {
        float hv = b1[l];
#pragma unroll
        for (int k = 0; k < KG_; k++) hv = fmaf(W1[l * KG_ + k], psi[k], hv);
        acc = fmaf(W2[l], gelu_exact(hv), acc);
    }
    return acc;
}

__global__ void build_vals_kernel(const float* __restrict__ muD, const float* __restrict__ sgD,
                                  const float* __restrict__ bD,
                                  const float* __restrict__ muE, const float* __restrict__ sgE,
                                  const float* __restrict__ bE,
                                  const float* __restrict__ W1, const float* __restrict__ b1,
                                  const float* __restrict__ W2, const float* __restrict__ b2) {
    int idx = blockIdx.x * blockDim.x + threadIdx.x;
    if (idx >= 2 * (LUTN + 1)) return;
    int which = idx / (LUTN + 1);
    int i = idx % (LUTN + 1);
    float b2v = b2[0];
    if (which == 0) {
        g_vals[0][i] = bias_eval((float)i * (RANGE_D / (float)LUTN), muD, sgD, bD, W1, b1, W2, b2v);
    } else {
        g_vals[1][i] = bias_eval((float)i * (RANGE_E / (float)LUTN), muE, sgE, bE, W1, b1, W2, b2v);
    }
}

__global__ void build_slopes_kernel() {
    int i = blockIdx.x * blockDim.x + threadIdx.x;
    if (i >= LUTN) return;
    float d0 = g_vals[0][i];
    g_lutD[i] = make_float2(d0, g_vals[0][i + 1] - d0);
    float e0 = g_vals[1][i];
    g_lutE[i] = make_float2(e0, g_vals[1][i + 1] - e0);
}

// ---------------------------------------------------------------------------
// Pre-split kernel: Q (scaled), K, V -> packed bf16 hi||lo rows (256 B/row).
// ---------------------------------------------------------------------------
__global__ __launch_bounds__(256) void presplit_kernel(
    const float* __restrict__ Qg, const float* __restrict__ Kg, const float* __restrict__ Vg) {
    int idx = blockIdx.x * blockDim.x + threadIdx.x;   // over H_*S_*16
    if (idx >= H_ * S_ * 16) return;
    int cg = idx & 15;
    int row = idx >> 4;
    const float qk_scale = 0.0883883476483184f;  // 1/sqrt(2*D)

    float4 q = *(const float4*)(Qg + (size_t)row * D_ + cg * 4);
    float4 kv = *(const float4*)(Kg + (size_t)row * D_ + cg * 4);
    float4 vv = *(const float4*)(Vg + (size_t)row * D_ + cg * 4);
    q.x *= qk_scale; q.y *= qk_scale; q.z *= qk_scale; q.w *= qk_scale;

    float h0, l0, h1, l1, h2, l2, h3, l3;
    uint2 w;
    split_bf(q.x, h0, l0); split_bf(q.y, h1, l1);
    split_bf(q.z, h2, l2); split_bf(q.w, h3, l3);
    w.x = pack_bf2(h0, h1); w.y = pack_bf2(h2, h3);
    *(uint2*)(g_Qsp + (size_t)row * 128 + cg * 4) = w;
    w.x = pack_bf2(l0, l1); w.y = pack_bf2(l2, l3);
    *(uint2*)(g_Qsp + (size_t)row * 128 + 64 + cg * 4) = w;

    split_bf(kv.x, h0, l0); split_bf(kv.y, h1, l1);
    split_bf(kv.z, h2, l2); split_bf(kv.w, h3, l3);
    w.x = pack_bf2(h0, h1); w.y = pack_bf2(h2, h3);
    *(uint2*)(g_Ksp + (size_t)row * 128 + cg * 4) = w;
    w.x = pack_bf2(l0, l1); w.y = pack_bf2(l2, l3);
    *(uint2*)(g_Ksp + (size_t)row * 128 + 64 + cg * 4) = w;

    split_bf(vv.x, h0, l0); split_bf(vv.y, h1, l1);
    split_bf(vv.z, h2, l2); split_bf(vv.w, h3, l3);
    w.x = pack_bf2(h0, h1); w.y = pack_bf2(h2, h3);
    *(uint2*)(g_Vsp + (size_t)row * 128 + cg * 4) = w;
    w.x = pack_bf2(l0, l1); w.y = pack_bf2(l2, l3);
    *(uint2*)(g_Vsp + (size_t)row * 128 + 64 + cg * 4) = w;
}

// ---------------------------------------------------------------------------
// Fused flash attention. BI=128, BJ=32, 8 warps; warp owns 16 rows x all cols.
// Softmax warp-local (no block barriers); double-buffered K/V cp.async.
// ---------------------------------------------------------------------------
__device__ __forceinline__ float lut_interp_g(const float2* __restrict__ lut, float x, float scale) {
    float t = x * scale;
    int ix = (int)t;
    ix = max(0, min(ix, LUTN - 1));
    float f = t - (float)ix;
    float2 e = __ldg(lut + ix);
    return fmaf(e.y, f, e.x);
}

__global__ __launch_bounds__(NT, 2) void attn_partial_kernel(
    const float* __restrict__ DMg, const float* __restrict__ EMg, const int* __restrict__ Mg) {
    extern __shared__ __nv_bfloat16 smem[];

    const int tid = threadIdx.x;
    const int lane = tid & 31;
    const int warp = tid >> 5;
    const int qr = lane >> 2;
    const int qc = lane & 3;

    const int h = blockIdx.y;
    const int i0 = blockIdx.x * BI;
    const int split = blockIdx.z;

    const float lscaleD = (float)LUTN / RANGE_D;
    const float lscaleE = (float)LUTN / RANGE_E;

    const uint32_t base_s = (uint32_t)__cvta_generic_to_shared(smem);
    const uint32_t qhi_s = base_s + OFF_QHI * 2;
    const uint32_t qlo_s = base_s + OFF_QLO * 2;
    const uint32_t khi_s = base_s + OFF_KHI * 2;
    const uint32_t klo_s = base_s + OFF_KLO * 2;
    const uint32_t vhi_s = base_s + OFF_VHI * 2;
    const uint32_t vlo_s = base_s + OFF_VLO * 2;
    const uint32_t phi_s = base_s + OFF_PHI * 2;
    const uint32_t plo_s = base_s + OFF_PLO * 2;

    // ldmatrix per-lane address components
    const uint32_t aoff_q = (uint32_t)((warp * 16 + (lane & 15)) * 144 + ((lane >> 4) << 4));
    const uint32_t aoff_p = (uint32_t)((warp * 16 + (lane & 15)) * 80 + ((lane >> 4) << 4));
    const uint32_t bk_base = ((lane >> 4) ? klo_s : khi_s)
                           + (uint32_t)((lane & 7) * 144 + (((lane >> 3) & 1) << 4));
    const uint32_t bv_base = ((lane >> 4) ? vlo_s : vhi_s)
                           + (uint32_t)((lane & 15) * 144);

    // cp.async copy pattern: 16B chunk c (0..15) of 256B row; c<8 -> hi else lo.
    const int st_row = tid >> 4;
    const int st_c = tid & 15;
    const uint32_t st_dhi = (uint32_t)((st_c & 7) * 16);
    const bool st_ishi = (st_c < 8);

    // Prologue: stage Q (128 rows) + K/V tile 0 (32 rows) as ONE group
    {
        const char* qsrc = (const char*)g_Qsp + ((size_t)(h * S_ + i0)) * 256;
#pragma unroll
        for (int k = 0; k < 8; k++) {
            int row = st_row + k * 16;
            cp_async16((st_ishi ? qhi_s : qlo_s) + (uint32_t)(row * 144) + st_dhi,
                       qsrc + (size_t)row * 256 + st_c * 16);
        }
        int j0 = split * TILES_PER_SPLIT * BJ;
        const char* ksrc = (const char*)g_Ksp + ((size_t)(h * S_ + j0)) * 256;
        const char* vsrc = (const char*)g_Vsp + ((size_t)(h * S_ + j0)) * 256;
#pragma unroll
        for (int k = 0; k < 2; k++) {
            int row = st_row + k * 16;
            uint32_t doff = (uint32_t)(row * 144) + st_dhi;
            cp_async16((st_ishi ? khi_s : klo_s) + doff, ksrc + (size_t)row * 256 + st_c * 16);
            cp_async16((st_ishi ? vhi_s : vlo_s) + doff, vsrc + (size_t)row * 256 + st_c * 16);
        }
        cp_commit();
    }

    float o[8][4];
#pragma unroll
    for (int cb = 0; cb < 8; cb++)
#pragma unroll
        for (int e = 0; e < 4; e++) o[cb][e] = 0.f;
    float m2[2] = {-1e30f, -1e30f};
    float l2a[2] = {0.f, 0.f};

    const int row0l = warp * 16 + qr;
    const int row1l = row0l + 8;

    for (int jt = 0; jt < TILES_PER_SPLIT; jt++) {
        const int j0 = (split * TILES_PER_SPLIT + jt) * BJ;
        const uint32_t bufo = (uint32_t)((jt & 1) * KVBUF_BYTES);

        // Bias + mask loads (LDG, overlap with cp.async wait)
        float2 dm2[2][4], em2[2][4];
        int2 mk2[2][4];
        {
            size_t rbase0 = ((size_t)h * S_ + (i0 + row0l)) * S_ + j0;
            size_t rbase1 = ((size_t)h * S_ + (i0 + row1l)) * S_ + j0;
#pragma unroll
            for (int cb = 0; cb < 4; cb++) {
                int colg = cb * 8 + qc * 2;
                dm2[0][cb] = *(const float2*)(DMg + rbase0 + colg);
                dm2[1][cb] = *(const float2*)(DMg + rbase1 + colg);
                em2[0][cb] = *(const float2*)(EMg + rbase0 + colg);
                em2[1][cb] = *(const float2*)(EMg + rbase1 + colg);
                mk2[0][cb] = *(const int2*)(Mg + rbase0 + colg);
                mk2[1][cb] = *(const int2*)(Mg + rbase1 + colg);
            }
        }

        cp_wait0();        // this tile's K/V group complete (own thread)
        __syncthreads();   // all threads' copies visible; prev buffer free

        // Issue next tile's K/V into the other buffer (no wait)
        if (jt + 1 < TILES_PER_SPLIT) {
            uint32_t nbufo = (uint32_t)(((jt + 1) & 1) * KVBUF_BYTES);
            const char* ksrc = (const char*)g_Ksp + ((size_t)(h * S_ + j0 + BJ)) * 256;
            const char* vsrc = (const char*)g_Vsp + ((size_t)(h * S_ + j0 + BJ)) * 256;
#pragma unroll
            for (int k = 0; k < 2; k++) {
                int row = st_row + k * 16;
                uint32_t doff = nbufo + (uint32_t)(row * 144) + st_dhi;
                cp_async16((st_ishi ? khi_s : klo_s) + doff, ksrc + (size_t)row * 256 + st_c * 16);
                cp_async16((st_ishi ? vhi_s : vlo_s) + doff, vsrc + (size_t)row * 256 + st_c * 16);
            }
            cp_commit();
        }

        // ---- QK^T: ldmatrix + bf16 mma (3-term) ----
        float sc[4][4];
#pragma unroll
        for (int cb = 0; cb < 4; cb++)
#pragma unroll
            for (int e = 0; e < 4; e++) sc[cb][e] = 0.f;

#pragma unroll
        for (int kk = 0; kk < 4; kk++) {
            uint32_t ah[4], al[4];
            ldsm_x4(qhi_s + aoff_q + kk * 32, ah);
            ldsm_x4(qlo_s + aoff_q + kk * 32, al);
#pragma unroll
            for (int cb = 0; cb < 4; cb++) {
                uint32_t b[4];
                ldsm_x4(bk_base + bufo + (uint32_t)(cb * 8 * 144) + kk * 32, b);
                mma_bf16(sc[cb], ah, b);
                mma_bf16(sc[cb], ah, b + 2);
                mma_bf16(sc[cb], al, b);
            }
        }

        // ---- LUT biases + mask ----
#pragma unroll
        for (int cb = 0; cb < 4; cb++) {
            float s0 = sc[cb][0] + lut_interp_g(g_lutD, dm2[0][cb].x, lscaleD)
                     + lut_interp_g(g_lutE, em2[0][cb].x, lscaleE);
            float s1 = sc[cb][1] + lut_interp_g(g_lutD, dm2[0][cb].y, lscaleD)
                     + lut_interp_g(g_lutE, em2[0][cb].y, lscaleE);
            float s2 = sc[cb][2] + lut_interp_g(g_lutD, dm2[1][cb].x, lscaleD)
                     + lut_interp_g(g_lutE, em2[1][cb].x, lscaleE);
            float s3 = sc[cb][3] + lut_interp_g(g_lutD, dm2[1][cb].y, lscaleD)
                     + lut_interp_g(g_lutE, em2[1][cb].y, lscaleE);
            sc[cb][0] = (mk2[0][cb].x == 0) ? -1e9f : s0;
            sc[cb][1] = (mk2[0][cb].y == 0) ? -1e9f : s1;
            sc[cb][2] = (mk2[1][cb].x == 0) ? -1e9f : s2;
            sc[cb][3] = (mk2[1][cb].y == 0) ? -1e9f : s3;
        }

        // ---- online softmax: fully warp-local (row = 4 lanes x 8 values) ----
        __syncwarp();  // prior PV ldmatrix done before P overwrite
        float corr2[2];
#pragma unroll
        for (int r = 0; r < 2; r++) {
            int e0 = r * 2, e1 = e0 + 1;
            int rowl = (r == 0) ? row0l : row1l;
            float v = fmaxf(fmaxf(sc[0][e0], sc[0][e1]), fmaxf(sc[1][e0], sc[1][e1]));
            v = fmaxf(v, fmaxf(fmaxf(sc[2][e0], sc[2][e1]), fmaxf(sc[3][e0], sc[3][e1])));
            v = fmaxf(v, __shfl_xor_sync(0xffffffffu, v, 1));
            v = fmaxf(v, __shfl_xor_sync(0xffffffffu, v, 2));
            float mnew = fmaxf(m2[r], v);
            corr2[r] = __expf(m2[r] - mnew);
            m2[r] = mnew;
            float ps = 0.f;
#pragma unroll
            for (int cb = 0; cb < 4; cb++) {
                float p0 = __expf(sc[cb][e0] - mnew);
                float p1 = __expf(sc[cb][e1] - mnew);
                sc[cb][e0] = p0;
                sc[cb][e1] = p1;
                ps += p0 + p1;
            }
            ps += __shfl_xor_sync(0xffffffffu, ps, 1);
            ps += __shfl_xor_sync(0xffffffffu, ps, 2);
            l2a[r] = l2a[r] * corr2[r] + ps;
#pragma unroll
            for (int cb = 0; cb < 4; cb++) {
                float h0, l0, h1, l1;
                split_bf(sc[cb][e0], h0, l0);
                split_bf(sc[cb][e1], h1, l1);
                int col = cb * 8 + qc * 2;
                *(uint32_t*)(smem + OFF_PHI + rowl * PS + col) = pack_bf2(h0, h1);
                *(uint32_t*)(smem + OFF_PLO + rowl * PS + col) = pack_bf2(l0, l1);
            }
        }
        // rescale O by correction factors
#pragma unroll
        for (int cb = 0; cb < 8; cb++) {
            o[cb][0] *= corr2[0]; o[cb][1] *= corr2[0];
            o[cb][2] *= corr2[1]; o[cb][3] *= corr2[1];
        }
        __syncwarp();  // P stores visible to warp's ldmatrix

        // ---- O += P * V: ldmatrix(+trans) + bf16 mma (3-term) ----
#pragma unroll
        for (int kk = 0; kk < 2; kk++) {
            uint32_t ah[4], al[4];
            ldsm_x4(phi_s + aoff_p + kk * 32, ah);
            ldsm_x4(plo_s + aoff_p + kk * 32, al);
#pragma unroll
            for (int cb = 0; cb < 8; cb++) {
                uint32_t b[4];
                // k-block step = 16 V-rows = 16*144 bytes (FIX: was 2304*2)
                ldsm_x4_trans(bv_base + bufo + (uint32_t)(kk * 16 * 144) + (uint32_t)(cb * 16), b);
                mma_bf16(o[cb], ah, b);
                mma_bf16(o[cb], ah, b + 2);
                mma_bf16(o[cb], al, b);
            }
        }
    }

    // ---- Epilogue: store un-normalized partial O + (m, l) ----
    float* Op = g_Opart[split];
    int ig0 = i0 + row0l;
    int ig1 = i0 + row1l;
#pragma unroll
    for (int cb = 0; cb < 8; cb++) {
        int dcol = cb * 8 + qc * 2;
        *(float2*)(Op + ((size_t)h * S_ + ig0) * D_ + dcol) = make_float2(o[cb][0], o[cb][1]);
        *(float2*)(Op + ((size_t)h * S_ + ig1) * D_ + dcol) = make_float2(o[cb][2], o[cb][3]);
    }
    if (qc == 0) {
        g_ML[split][h * S_ + ig0] = make_float2(m2[0], l2a[0]);
        g_ML[split][h * S_ + ig1] = make_float2(m2[1], l2a[1]);
    }
}

// ---------------------------------------------------------------------------
// Combine pass: merge NSPLIT partial softmax results. 2 rows per thread (MLP).
// ---------------------------------------------------------------------------
#define COMB_N (H_ * S_ * (D_ / 4))
__global__ __launch_bounds__(256) void combine_kernel(float* __restrict__ Og) {
    int idx0 = blockIdx.x * blockDim.x + threadIdx.x;
#pragma unroll
    for (int half = 0; half < 2; half++) {
        int idx = idx0 + half * (COMB_N / 2);
        int row = idx >> 4;
        int dcol = (idx & 15) * 4;

        float2 ml[NSPLIT];
        float m = -1e30f;
#pragma unroll
        for (int s = 0; s < NSPLIT; s++) {
            ml[s] = g_ML[s][row];
            m = fmaxf(m, ml[s].x);
        }
        float a[NSPLIT];
        float den = 0.f;
#pragma unroll
        for (int s = 0; s < NSPLIT; s++) {
            a[s] = __expf(ml[s].x - m);
            den = fmaf(ml[s].y, a[s], den);
        }
        float inv = 1.0f / den;

        float4 r = make_float4(0.f, 0.f, 0.f, 0.f);
#pragma unroll
        for (int s = 0; s < NSPLIT; s++) {
            float4 os = *(const float4*)&g_Opart[s][(size_t)row * D_ + dcol];
            r.x = fmaf(os.x, a[s], r.x);
            r.y = fmaf(os.y, a[s], r.y);
            r.z = fmaf(os.z, a[s], r.z);
            r.w = fmaf(os.w, a[s], r.w);
        }
        r.x *= inv; r.y *= inv; r.z *= inv; r.w *= inv;
        *(float4*)(Og + (size_t)row * D_ + dcol) = r;
    }
}

// ---------------------------------------------------------------------------
// kernel_launch
// Input order: Q, K, V, distance_matrix, energy_matrix, mask,
//              mu_D, sigma_D, b_D, mu_E, sigma_E, b_E, W1, b1, W2, b2
// ---------------------------------------------------------------------------
extern "C" void kernel_launch(void* const* d_in, const int* in_sizes, int n_in,
                              void* d_out, int out_size) {
    const float* Q  = (const float*)d_in[0];
    const float* K  = (const float*)d_in[1];
    const float* V  = (const float*)d_in[2];
    const float* DM = (const float*)d_in[3];
    const float* EM = (const float*)d_in[4];
    const int*   MK = (const int*)d_in[5];
    const float* muD = (const float*)d_in[6];
    const float* sgD = (const float*)d_in[7];
    const float* bD  = (const float*)d_in[8];
    const float* muE = (const float*)d_in[9];
    const float* sgE = (const float*)d_in[10];
    const float* bE  = (const float*)d_in[11];
    const float* W1  = (const float*)d_in[12];
    const float* b1  = (const float*)d_in[13];
    const float* W2  = (const float*)d_in[14];
    const float* b2  = (const float*)d_in[15];
    float* Og = (float*)d_out;

    const int smem_bytes = SMEM_ELEMS * 2;   // 94208 B

    cudaFuncSetAttribute(attn_partial_kernel, cudaFuncAttributeMaxDynamicSharedMemorySize, smem_bytes);

    int nev = 2 * (LUTN + 1);
    build_vals_kernel<<<(nev + 255) / 256, 256>>>(muD, sgD, bD, muE, sgE, bE, W1, b1, W2, b2);
    build_slopes_kernel<<<(LUTN + 255) / 256, 256>>>();
    presplit_kernel<<<(H_ * S_ * 16 + 255) / 256, 256>>>(Q, K, V);

    dim3 grid(S_ / BI, H_, NSPLIT);
    attn_partial_kernel<<<grid, NT, smem_bytes>>>(DM, EM, MK);

    combine_kernel<<<(COMB_N / 2 + 255) / 256, 256>>>(Og);
}